// round 17
// baseline (speedup 1.0000x reference)
#include <cuda_runtime.h>

// ---------------- problem constants ----------------
#define T_STEPS 192
#define B_SZ    128
#define IN_SZ   512
#define R_SZ    1024
#define OUT_SZ  100
#define PS      64
#define BR      (B_SZ * R_SZ)          // 131072
#define SPK_ELEMS (T_STEPS * BR)       // 25165824
#define OUT_ELEMS (B_SZ * OUT_SZ)      // 12800
#define ALPHA 0.9f
#define BETA  0.9f

#define GK 256                 // K per split chunk (association FROZEN)
#define NSPLIT_MAX 8
#define TSTRIDE 68             // smem row stride (64 + pad)
#define NBLK 256               // persistent scan grid

// ---------------- device scratch ----------------
__device__ float g_cur[T_STEPS * BR];    // input projection (+b_in)
__device__ float g_spk[T_STEPS * BR];    // spike history fp32
__device__ float g_syn[BR];
__device__ float g_mem[BR];
__device__ float g_part[NSPLIT_MAX * BR];// split-K partials
__device__ float g_ro[B_SZ * 3 * R_SZ];  // readout input
__device__ unsigned g_bar_count;
__device__ unsigned g_bar_phase;

typedef unsigned long long ull;

__device__ __forceinline__ ull pack2(float lo, float hi) {
    ull r; asm("mov.b64 %0, {%1,%2};" : "=l"(r) : "f"(lo), "f"(hi)); return r;
}
__device__ __forceinline__ void fma2(ull &d, ull a, ull b) {
    asm("fma.rn.f32x2 %0, %1, %2, %0;" : "+l"(d) : "l"(a), "l"(b));
}
__device__ __forceinline__ float2 unpack2(ull v) {
    float2 r; asm("mov.b64 {%0,%1}, %2;" : "=f"(r.x), "=f"(r.y) : "l"(v)); return r;
}

// ---------------- grid barrier (all NBLK CTAs resident) ----------------
__device__ __forceinline__ void grid_bar(unsigned target) {
    __threadfence();
    __syncthreads();
    if (threadIdx.x == 0) {
        unsigned t = atomicAdd(&g_bar_count, 1u);
        if (t == NBLK - 1) {
            g_bar_count = 0;
            __threadfence();
            atomicExch(&g_bar_phase, target);
        } else {
            while (atomicAdd(&g_bar_phase, 0u) < target) { __nanosleep(64); }
        }
        __threadfence();
    }
    __syncthreads();
}

// ---------------- init: zero syn/mem + barrier state ----------------
__global__ void k_init() {
    int i = blockIdx.x * blockDim.x + threadIdx.x;
    float4 z = make_float4(0.f, 0.f, 0.f, 0.f);
    *(float4*)(g_syn + i * 4) = z;
    *(float4*)(g_mem + i * 4) = z;
    if (i == 0) { g_bar_count = 0; g_bar_phase = 0; }
}

// ---------------- input projection GEMM (R1 engine) ----------------
__global__ void k_input_gemm(const float* __restrict__ X,
                             const float* __restrict__ Win,
                             const float* __restrict__ bin) {
    __shared__ float As[16][128];
    __shared__ float Bs[16][128];
    int tid = threadIdx.x;
    int n0 = blockIdx.x * 128;
    int m0 = blockIdx.y * 128;
    int p  = m0 >> 13;
    const float* A = X + (size_t)m0 * IN_SZ;
    const float* W = Win + (size_t)p * R_SZ * IN_SZ + (size_t)n0 * IN_SZ;

    int lr = tid >> 2;
    int lk = (tid & 3) * 4;
    int tx = tid & 15, ty = tid >> 4;

    ull acc[8][4];
#pragma unroll
    for (int i = 0; i < 8; i++)
#pragma unroll
        for (int j = 0; j < 4; j++) acc[i][j] = 0ULL;

    for (int k0 = 0; k0 < IN_SZ; k0 += 16) {
        float4 a0 = *(const float4*)(A + (size_t)lr * IN_SZ + k0 + lk);
        float4 a1 = *(const float4*)(A + (size_t)(lr + 64) * IN_SZ + k0 + lk);
        float4 b0 = *(const float4*)(W + (size_t)lr * IN_SZ + k0 + lk);
        float4 b1 = *(const float4*)(W + (size_t)(lr + 64) * IN_SZ + k0 + lk);
        __syncthreads();
        As[lk + 0][lr] = a0.x; As[lk + 1][lr] = a0.y; As[lk + 2][lr] = a0.z; As[lk + 3][lr] = a0.w;
        As[lk + 0][lr + 64] = a1.x; As[lk + 1][lr + 64] = a1.y; As[lk + 2][lr + 64] = a1.z; As[lk + 3][lr + 64] = a1.w;
        Bs[lk + 0][lr] = b0.x; Bs[lk + 1][lr] = b0.y; Bs[lk + 2][lr] = b0.z; Bs[lk + 3][lr] = b0.w;
        Bs[lk + 0][lr + 64] = b1.x; Bs[lk + 1][lr + 64] = b1.y; Bs[lk + 2][lr + 64] = b1.z; Bs[lk + 3][lr + 64] = b1.w;
        __syncthreads();
#pragma unroll
        for (int kk = 0; kk < 16; kk++) {
            float4 af0 = *(float4*)&As[kk][ty * 8];
            float4 af1 = *(float4*)&As[kk][ty * 8 + 4];
            float4 bf0 = *(float4*)&Bs[kk][tx * 8];
            float4 bf1 = *(float4*)&Bs[kk][tx * 8 + 4];
            ull b2[4] = { pack2(bf0.x, bf0.y), pack2(bf0.z, bf0.w),
                          pack2(bf1.x, bf1.y), pack2(bf1.z, bf1.w) };
            float am[8] = { af0.x, af0.y, af0.z, af0.w, af1.x, af1.y, af1.z, af1.w };
#pragma unroll
            for (int i = 0; i < 8; i++) {
                ull a2 = pack2(am[i], am[i]);
#pragma unroll
                for (int j = 0; j < 4; j++) fma2(acc[i][j], a2, b2[j]);
            }
        }
    }
    float* C = g_cur + (size_t)m0 * R_SZ + n0;
#pragma unroll
    for (int i = 0; i < 8; i++) {
        int m = ty * 8 + i;
#pragma unroll
        for (int j = 0; j < 4; j++) {
            float2 v = unpack2(acc[i][j]);
            int n = tx * 8 + j * 2;
            C[(size_t)m * R_SZ + n]     = v.x + __ldg(bin + n0 + n);
            C[(size_t)m * R_SZ + n + 1] = v.y + __ldg(bin + n0 + n + 1);
        }
    }
}

// ---------------- persistent scan: R13 gemm + R13 update, grid barriers ------
// 256 CTAs x 256 threads, 2 CTAs/SM guaranteed. CTA: ks=bid>>5, mt=(bid>>4)&1,
// nt=bid&15. Per step: gemm partial (R13 engine verbatim) -> barrier ->
// elementwise update (R13 k_update body, idx = bid*512 + tid*2) -> barrier.
__global__ void __launch_bounds__(256, 2)
k_scan(const float* __restrict__ Wrec,
       const float* __restrict__ Wlin,
       const float* __restrict__ brec,
       float* __restrict__ spk_out) {
    const int bid = blockIdx.x;
    const int tid = threadIdx.x;
    const int ks = bid >> 5;
    const int mt = (bid >> 4) & 1;
    const int nt = bid & 15;

    __shared__ float As[2][32 * TSTRIDE];
    __shared__ float Ws[2][32 * TSTRIDE];

    const int lrw = tid >> 2;
    const int lkq = (tid & 3) * 2;
    const int tx = tid & 15, ty = tid >> 4;

    // update-phase element base
    const size_t ue = (size_t)bid * 512 + (size_t)tid * 2;
    const int ur = (int)(ue & (R_SZ - 1));
    const float2 ubr = *(const float2*)(brec + ur);

    for (int t = 0; t < T_STEPS; t++) {
        const int nsplit = (t == 0) ? 0 : ((t > PS) ? 8 : 4);

        // ---- gemm phase (R13 engine verbatim) ----
        if (ks < nsplit) {
            const int tsrc = (ks < 4) ? (t - 1) : (t - PS);
            const int kofs = (ks & 3) * GK;
            const float* Asrc = g_spk + (size_t)tsrc * BR + (size_t)(mt * 64) * R_SZ + kofs;
            const float* Wsrc = ((ks < 4) ? Wrec : Wlin) + (size_t)(nt * 64) * R_SZ + kofs;

            ull acc[4][2];
#pragma unroll
            for (int i = 0; i < 4; i++) { acc[i][0] = 0ULL; acc[i][1] = 0ULL; }

            float4 ar[2], wr[2];
#pragma unroll
            for (int j = 0; j < 2; j++) {
                ar[j] = *(const float4*)(Asrc + (size_t)lrw * R_SZ + (lkq + j) * 4);
                wr[j] = *(const float4*)(Wsrc + (size_t)lrw * R_SZ + (lkq + j) * 4);
            }
#pragma unroll
            for (int j = 0; j < 2; j++) {
                int kk = (lkq + j) * 4;
                As[0][(kk + 0) * TSTRIDE + lrw] = ar[j].x;
                As[0][(kk + 1) * TSTRIDE + lrw] = ar[j].y;
                As[0][(kk + 2) * TSTRIDE + lrw] = ar[j].z;
                As[0][(kk + 3) * TSTRIDE + lrw] = ar[j].w;
                Ws[0][(kk + 0) * TSTRIDE + lrw] = wr[j].x;
                Ws[0][(kk + 1) * TSTRIDE + lrw] = wr[j].y;
                Ws[0][(kk + 2) * TSTRIDE + lrw] = wr[j].z;
                Ws[0][(kk + 3) * TSTRIDE + lrw] = wr[j].w;
            }
            __syncthreads();

#pragma unroll
            for (int s = 0; s < 8; s++) {
                if (s + 1 < 8) {
                    const float* An = Asrc + (size_t)lrw * R_SZ + (s + 1) * 32;
                    const float* Wn = Wsrc + (size_t)lrw * R_SZ + (s + 1) * 32;
#pragma unroll
                    for (int j = 0; j < 2; j++) {
                        ar[j] = *(const float4*)(An + (lkq + j) * 4);
                        wr[j] = *(const float4*)(Wn + (lkq + j) * 4);
                    }
                }
                const float* a_ = As[s & 1];
                const float* w_ = Ws[s & 1];
#pragma unroll 8
                for (int kk = 0; kk < 32; kk++) {
                    float4 a = *(const float4*)(a_ + kk * TSTRIDE + ty * 4);
                    float4 w = *(const float4*)(w_ + kk * TSTRIDE + tx * 4);
                    ull wb0 = pack2(w.x, w.y);
                    ull wb1 = pack2(w.z, w.w);
                    float am4[4] = { a.x, a.y, a.z, a.w };
#pragma unroll
                    for (int i = 0; i < 4; i++) {
                        ull a2 = pack2(am4[i], am4[i]);
                        fma2(acc[i][0], a2, wb0);
                        fma2(acc[i][1], a2, wb1);
                    }
                }
                if (s + 1 < 8) {
                    float* ad = As[(s + 1) & 1];
                    float* wd = Ws[(s + 1) & 1];
#pragma unroll
                    for (int j = 0; j < 2; j++) {
                        int kk = (lkq + j) * 4;
                        ad[(kk + 0) * TSTRIDE + lrw] = ar[j].x;
                        ad[(kk + 1) * TSTRIDE + lrw] = ar[j].y;
                        ad[(kk + 2) * TSTRIDE + lrw] = ar[j].z;
                        ad[(kk + 3) * TSTRIDE + lrw] = ar[j].w;
                        wd[(kk + 0) * TSTRIDE + lrw] = wr[j].x;
                        wd[(kk + 1) * TSTRIDE + lrw] = wr[j].y;
                        wd[(kk + 2) * TSTRIDE + lrw] = wr[j].z;
                        wd[(kk + 3) * TSTRIDE + lrw] = wr[j].w;
                    }
                }
                __syncthreads();
            }

            float* C = g_part + (size_t)ks * BR + (size_t)(mt * 64) * R_SZ + nt * 64;
#pragma unroll
            for (int i = 0; i < 4; i++) {
                int m = ty * 4 + i;
                float2 v01 = unpack2(acc[i][0]);
                float2 v23 = unpack2(acc[i][1]);
                float4 v = make_float4(v01.x, v01.y, v23.x, v23.y);
                *(float4*)(C + (size_t)m * R_SZ + tx * 4) = v;
            }
        }

        grid_bar((unsigned)(2 * t + 1));

        // ---- update phase (R13 k_update body verbatim) ----
        {
            float2 cur = *(const float2*)(g_cur + (size_t)t * BR + ue);
            float2 s = make_float2(0.f, 0.f);
            if (nsplit == 8) {
#pragma unroll
                for (int k2 = 0; k2 < 8; k2++) {
                    float2 pv = *(const float2*)(g_part + (size_t)k2 * BR + ue);
                    s.x += pv.x; s.y += pv.y;
                }
            } else if (nsplit == 4) {
#pragma unroll
                for (int k2 = 0; k2 < 4; k2++) {
                    float2 pv = *(const float2*)(g_part + (size_t)k2 * BR + ue);
                    s.x += pv.x; s.y += pv.y;
                }
            }
            float2 syn = *(float2*)(g_syn + ue);
            float2 mem = *(float2*)(g_mem + ue);

            float2 spk;
            syn.x = ALPHA * syn.x + cur.x + s.x + ubr.x;
            float rs = (mem.x > 1.0f) ? 1.0f : 0.0f;
            mem.x = BETA * mem.x + syn.x - rs;
            spk.x = (mem.x > 1.0f) ? 1.0f : 0.0f;

            syn.y = ALPHA * syn.y + cur.y + s.y + ubr.y;
            rs = (mem.y > 1.0f) ? 1.0f : 0.0f;
            mem.y = BETA * mem.y + syn.y - rs;
            spk.y = (mem.y > 1.0f) ? 1.0f : 0.0f;

            *(float2*)(g_syn + ue) = syn;
            *(float2*)(g_mem + ue) = mem;
            *(float2*)(g_spk + (size_t)t * BR + ue) = spk;
            if (spk_out) *(float2*)(spk_out + (size_t)t * BR + ue) = spk;
        }

        grid_bar((unsigned)(2 * t + 2));
    }
}

// ---------------- readout mean over each partition ----------------
__global__ void k_ro_reduce() {
    int e = (blockIdx.x * 256 + threadIdx.x) * 4;   // over B*3R = 393216
    int b = e / (3 * R_SZ);
    int c = e % (3 * R_SZ);
    int p = c >> 10;
    int r = c & (R_SZ - 1);
    const float* base = g_spk + ((size_t)(p * PS) * B_SZ + b) * R_SZ + r;
    float4 s = make_float4(0.f, 0.f, 0.f, 0.f);
#pragma unroll 8
    for (int st = 0; st < PS; st++) {
        float4 v = *(const float4*)(base + (size_t)st * BR);
        s.x += v.x; s.y += v.y; s.z += v.z; s.w += v.w;
    }
    float inv = 1.0f / (float)PS;
    s.x *= inv; s.y *= inv; s.z *= inv; s.w *= inv;
    *(float4*)(g_ro + e) = s;
}

// ---------------- final readout GEMM + softmax ----------------
__global__ void k_readout(float* __restrict__ out,
                          const float* __restrict__ Wro,
                          const float* __restrict__ bro) {
    int b = blockIdx.x;
    __shared__ float ro_s[3 * R_SZ];
    __shared__ float logit[112];
    __shared__ float red_sum;
    int tid = threadIdx.x;  // 128 threads

    for (int i = tid * 4; i < 3 * R_SZ; i += 512)
        *(float4*)&ro_s[i] = *(const float4*)(g_ro + (size_t)b * 3 * R_SZ + i);
    __syncthreads();

    int warp = tid >> 5, lane = tid & 31;
    for (int o = warp; o < OUT_SZ; o += 4) {
        const float* w = Wro + (size_t)o * (3 * R_SZ);
        float p0 = 0.f;
        for (int k = lane; k < 3 * R_SZ; k += 32) p0 += ro_s[k] * __ldg(w + k);
#pragma unroll
        for (int off = 16; off; off >>= 1) p0 += __shfl_xor_sync(0xffffffffu, p0, off);
        if (lane == 0) logit[o] = p0 + __ldg(bro + o);
    }
    __syncthreads();
    if (warp == 0) {
        float m = -1e30f;
        for (int i = lane; i < OUT_SZ; i += 32) m = fmaxf(m, logit[i]);
#pragma unroll
        for (int off = 16; off; off >>= 1) m = fmaxf(m, __shfl_xor_sync(0xffffffffu, m, off));
        float sm = 0.f;
        for (int i = lane; i < OUT_SZ; i += 32) {
            float e = expf(logit[i] - m);
            logit[i] = e;
            sm += e;
        }
#pragma unroll
        for (int off = 16; off; off >>= 1) sm += __shfl_xor_sync(0xffffffffu, sm, off);
        if (lane == 0) red_sum = sm;
    }
    __syncthreads();
    float inv = 1.0f / red_sum;
    for (int i = tid; i < OUT_SZ; i += 128)
        out[(size_t)b * OUT_SZ + i] = logit[i] * inv;
}

// ---------------- launcher ----------------
extern "C" void kernel_launch(void* const* d_in, const int* in_sizes, int n_in,
                              void* d_out, int out_size) {
    const float* x     = (const float*)d_in[0];
    const float* W_in  = (const float*)d_in[1];
    const float* b_in  = (const float*)d_in[2];
    const float* W_lin = (const float*)d_in[3];
    const float* W_rec = (const float*)d_in[4];
    const float* b_rec = (const float*)d_in[5];
    const float* W_ro  = (const float*)d_in[6];
    const float* b_ro  = (const float*)d_in[7];

    float* out_main = (float*)d_out;
    float* spk_out  = nullptr;
    if (out_size >= OUT_ELEMS + SPK_ELEMS) {
        spk_out = (float*)d_out + OUT_ELEMS;
    } else if (out_size == SPK_ELEMS) {
        spk_out = (float*)d_out;
        out_main = nullptr;
    }

    k_init<<<128, 256>>>();
    k_input_gemm<<<dim3(R_SZ / 128, (T_STEPS * B_SZ) / 128), 256>>>(x, W_in, b_in);
    k_scan<<<NBLK, 256>>>(W_rec, W_lin, b_rec, spk_out);
    k_ro_reduce<<<384, 256>>>();
    if (out_main) k_readout<<<B_SZ, 128>>>(out_main, W_ro, b_ro);
}